// round 16
// baseline (speedup 1.0000x reference)
#include <cuda_runtime.h>
#include <cuda_fp16.h>
#include <float.h>
#include <stdint.h>

#define NODES 65536
#define HD 128
#define THREADS 256
#define TSH 68                       // uint32 (half2) stride per 128-half row
#define STGH 132                     // fp16 staging stride (halves)
#define MAXEDGES (1048576 + NODES)
#define GRID_EDGE 304
#define BMAX 24                      // max distinct dst rows cached in smem

// edge kernel smem map (bytes)
#define HBUF (128 * TSH * 4)         // 34816
#define SM_T 2048
#define SM_W (2048 + HBUF)
#define STG_BYTES (64 * STGH * 2)    // 16896
#define SM_STG0 (2048 + 2 * HBUF)
#define SM_STG1 (SM_STG0 + STG_BYTES)
#define SM_B (SM_STG0 + 2 * STG_BYTES)
#define SB_BYTES (BMAX * TSH * 4)    // 6528
#define EDGE_SMEM (SM_B + SB_BYTES)  // 112000 -> 2 CTAs/SM

// node GEMM smem: header(1024) + sA + WH + WL   -> 2 CTAs/SM
#define AB_SA 1024
#define AB_WH (1024 + HBUF)
#define AB_WL (1024 + 2 * HBUF)
#define AB_SMEM (1024 + 3 * HBUF)    // 105472

// ---------------- scratch ----------------
__device__ __half g_Ah[(size_t)NODES * HD];
__device__ __half g_Bh[(size_t)NODES * HD];
__device__ float g_agg[(size_t)NODES * HD];
__device__ float g_h0[(size_t)NODES * HD];
__device__ __half g_w2t[HD * HD];
__device__ __half g_whA[HD * 256];
__device__ __half g_wlA[HD * 256];
__device__ __half g_wh1[HD * HD];
__device__ __half g_wl1[HD * HD];
__device__ __half g_wh2[HD * HD];
__device__ __half g_wl2[HD * HD];
__device__ int g_cnt[NODES];
__device__ int g_next[NODES];
__device__ int g_ssrc[MAXEDGES];
__device__ int g_sdst[MAXEDGES];

__global__ __launch_bounds__(THREADS) void fill_kernel(float4* p, float v, int n4) {
    int i = blockIdx.x * blockDim.x + threadIdx.x;
    if (i < n4) p[i] = make_float4(v, v, v, v);
}

__global__ __launch_bounds__(THREADS) void zero_i32(int* p, int n) {
    int i = blockIdx.x * blockDim.x + threadIdx.x;
    if (i < n) p[i] = 0;
}

// ---------------- counting sort by dst (once per launch) ----------------
__global__ __launch_bounds__(THREADS) void hist_kernel(
    const int* __restrict__ ei, int* __restrict__ cnt, int E, int total)
{
    int e = blockIdx.x * blockDim.x + threadIdx.x;
    if (e < total) {
        int d = (e < E) ? ei[E + e] : (e - E);
        atomicAdd(&cnt[d], 1);
    }
}

#define SCAN_T 1024
#define CHUNK (NODES / SCAN_T)   // 64
__global__ __launch_bounds__(SCAN_T) void scan_kernel(
    const int* __restrict__ cnt, int* __restrict__ next)
{
    __shared__ int part[SCAN_T];
    int t = threadIdx.x;
    int base = t * CHUNK;
    int sum = 0;
#pragma unroll 4
    for (int i = 0; i < CHUNK; i++) sum += cnt[base + i];
    part[t] = sum;
    __syncthreads();
    for (int off = 1; off < SCAN_T; off <<= 1) {
        int v = (t >= off) ? part[t - off] : 0;
        __syncthreads();
        part[t] += v;
        __syncthreads();
    }
    int off = part[t] - sum;   // exclusive
#pragma unroll 4
    for (int i = 0; i < CHUNK; i++) {
        next[base + i] = off;
        off += cnt[base + i];
    }
}

__global__ __launch_bounds__(THREADS) void scatter_kernel(
    const int* __restrict__ ei, int* __restrict__ next,
    int* __restrict__ ssrc, int* __restrict__ sdst, int E, int total)
{
    int e = blockIdx.x * blockDim.x + threadIdx.x;
    if (e < total) {
        int s, d;
        if (e < E) { s = ei[e]; d = ei[E + e]; }
        else       { s = e - E; d = s; }
        int pos = atomicAdd(&next[d], 1);
        ssrc[pos] = s;
        sdst[pos] = d;
    }
}

// ---------------- unified weight prep ----------------
__global__ __launch_bounds__(HD) void prep_all_kernel(
    const float* __restrict__ lw1, const float* __restrict__ lw2,
    const float* __restrict__ gw1, const float* __restrict__ gw2,
    __half* __restrict__ whA, __half* __restrict__ wlA,
    __half* __restrict__ w2t,
    __half* __restrict__ wh1, __half* __restrict__ wl1,
    __half* __restrict__ wh2, __half* __restrict__ wl2)
{
    int b = blockIdx.x, n = threadIdx.x;
    if (b < 256) {
        int k = b;
        float v = lw1[k * HD + n];
        __half h = __float2half_rn(v);
        whA[n * 256 + k] = h;
        wlA[n * 256 + k] = __float2half_rn(v - __half2float(h));
    } else if (b < 384) {
        int nn = b - 256;
        w2t[nn * HD + n] = __float2half(lw2[n * HD + nn]);
    } else if (b < 512) {
        int k = b - 384;
        float v = gw1[k * HD + n];
        __half h = __float2half_rn(v);
        wh1[n * HD + k] = h;
        wl1[n * HD + k] = __float2half_rn(v - __half2float(h));
    } else {
        int k = b - 512;
        float v = gw2[k * HD + n];
        __half h = __float2half_rn(v);
        wh2[n * HD + k] = h;
        wl2[n * HD + k] = __float2half_rn(v - __half2float(h));
    }
}

// ---------------- mma / ldmatrix helpers ----------------
__device__ __forceinline__ void mma_fp16(float* d, const uint32_t* a, const uint32_t* b) {
    asm volatile(
        "mma.sync.aligned.m16n8k16.row.col.f32.f16.f16.f32 "
        "{%0,%1,%2,%3}, {%4,%5,%6,%7}, {%8,%9}, {%0,%1,%2,%3};"
        : "+f"(d[0]), "+f"(d[1]), "+f"(d[2]), "+f"(d[3])
        : "r"(a[0]), "r"(a[1]), "r"(a[2]), "r"(a[3]), "r"(b[0]), "r"(b[1]));
}

__device__ __forceinline__ void ldsm_x4(uint32_t addr, uint32_t* r) {
    asm volatile(
        "ldmatrix.sync.aligned.m8n8.x4.shared.b16 {%0,%1,%2,%3}, [%4];"
        : "=r"(r[0]), "=r"(r[1]), "=r"(r[2]), "=r"(r[3]) : "r"(addr));
}

__device__ __forceinline__ void atomic_fmax(float* p, float v) {
    if (v >= 0.f) atomicMax((int*)p, __float_as_int(v));
    else          atomicMin((unsigned int*)p, __float_as_uint(v));
}

__device__ __forceinline__ uint32_t smem_u32(const void* p) {
    uint32_t a;
    asm("{ .reg .u64 t; cvta.to.shared.u64 t, %1; cvt.u32.u64 %0, t; }"
        : "=r"(a) : "l"(p));
    return a;
}

struct LaneC { int rA, kA, rB, kB; };
__device__ __forceinline__ LaneC lane_consts(int lane) {
    LaneC c;
    c.rA = lane & 15;
    c.kA = (lane >> 4) * 4;
    c.rB = (lane & 7) + ((lane >> 4) << 3);
    c.kB = ((lane >> 3) & 1) * 4;
    return c;
}

// 8-kstep MMA block with hi/lo split weights (node GEMMs)
__device__ __forceinline__ void mma_block_hl(
    uint32_t aSA, uint32_t aWH, uint32_t aWL,
    float acc[4][4][4], int warpRow, int warpCol, const LaneC& L)
{
#pragma unroll
    for (int ks = 0; ks < 8; ks++) {
        int base = ks * 8;
        uint32_t bh[4][2], bl[4][2];
#pragma unroll
        for (int p = 0; p < 2; p++) {
            uint32_t r[4];
            uint32_t off = (uint32_t)(((warpCol + p * 16 + L.rB) * TSH + base + L.kB) * 4);
            ldsm_x4(aWH + off, r);
            bh[2*p][0] = r[0]; bh[2*p][1] = r[1];
            bh[2*p+1][0] = r[2]; bh[2*p+1][1] = r[3];
            ldsm_x4(aWL + off, r);
            bl[2*p][0] = r[0]; bl[2*p][1] = r[1];
            bl[2*p+1][0] = r[2]; bl[2*p+1][1] = r[3];
        }
        uint32_t a[4][4];
#pragma unroll
        for (int mf = 0; mf < 4; mf++) {
            uint32_t off = (uint32_t)(((warpRow + mf * 16 + L.rA) * TSH + base + L.kA) * 4);
            ldsm_x4(aSA + off, a[mf]);
        }
#pragma unroll
        for (int mf = 0; mf < 4; mf++)
#pragma unroll
            for (int nf = 0; nf < 4; nf++) {
                mma_fp16(acc[mf][nf], a[mf], bh[nf]);
                mma_fp16(acc[mf][nf], a[mf], bl[nf]);
            }
    }
}

__device__ __forceinline__ void async_w_tile(
    uint32_t dstH, uint32_t dstL,
    const __half* __restrict__ srcH, const __half* __restrict__ srcL,
    int srcStride, int tid)
{
#pragma unroll
    for (int it = 0; it < 8; it++) {
        int lin = tid + it * THREADS;
        int n = lin >> 4, c = lin & 15;
        uint32_t off = (uint32_t)(n * (TSH * 4) + c * 16);
        asm volatile("cp.async.cg.shared.global [%0], [%1], 16;"
                     :: "r"(dstH + off), "l"(srcH + (size_t)n * srcStride + c * 8));
        asm volatile("cp.async.cg.shared.global [%0], [%1], 16;"
                     :: "r"(dstL + off), "l"(srcL + (size_t)n * srcStride + c * 8));
    }
    asm volatile("cp.async.commit_group;" ::: "memory");
}

__device__ __forceinline__ void load_in_tile(
    const float* __restrict__ In, int rowBase, uint32_t* sA, int tid)
{
    int r = tid >> 1, h = tid & 1;
    const float4* src = (const float4*)(In + (size_t)(rowBase + r) * HD + h * 64);
    uint32_t* dst = sA + r * TSH + h * 32;
#pragma unroll
    for (int j = 0; j < 8; j++) {
        float4 v0 = src[j * 2], v1 = src[j * 2 + 1];
        __half2 a = __floats2half2_rn(v0.x, v0.y);
        __half2 b = __floats2half2_rn(v0.z, v0.w);
        __half2 c = __floats2half2_rn(v1.x, v1.y);
        __half2 d = __floats2half2_rn(v1.z, v1.w);
        uint4 u = make_uint4(*(uint32_t*)&a, *(uint32_t*)&b,
                             *(uint32_t*)&c, *(uint32_t*)&d);
        *(uint4*)(dst + j * 4) = u;
    }
}

// ---------------- fused A/B node GEMM (2 CTAs/SM, sequential W) ----------------
__global__ __launch_bounds__(THREADS, 2) void gemm_ab_kernel(
    const float* __restrict__ pos, const float* __restrict__ inx,
    const __half* __restrict__ WHA, const __half* __restrict__ WLA,
    const float* __restrict__ lb1,
    __half* __restrict__ Ah, __half* __restrict__ Bh)
{
    extern __shared__ char sm[];
    float* sBias = (float*)sm;
    uint32_t sb = smem_u32(sm);
    uint32_t aSA = sb + AB_SA;
    uint32_t aWH = sb + AB_WH, aWL = sb + AB_WL;
    uint32_t* sA = (uint32_t*)(sm + AB_SA);

    int tid = threadIdx.x, lane = tid & 31, wid = tid >> 5;
    int rowBase = blockIdx.x * 128;

    async_w_tile(aWH, aWL, WHA + 128, WLA + 128, 256, tid);   // Wp

    if (tid < 128) sBias[tid] = lb1[tid];
    load_in_tile(pos, rowBase, sA, tid);

    asm volatile("cp.async.wait_group 0;" ::: "memory");
    __syncthreads();

    int warpRow = (wid & 1) * 64, warpCol = (wid >> 1) * 32;
    int g = lane >> 2, tg = lane & 3;
    LaneC L = lane_consts(lane);

    float acc[4][4][4];
#pragma unroll
    for (int i = 0; i < 4; i++)
#pragma unroll
        for (int j = 0; j < 4; j++)
#pragma unroll
            for (int q = 0; q < 4; q++) acc[i][j][q] = 0.f;

    mma_block_hl(aSA, aWH, aWL, acc, warpRow, warpCol, L);

#pragma unroll
    for (int mf = 0; mf < 4; mf++) {
        size_t r0 = (size_t)rowBase + warpRow + mf * 16 + g;
#pragma unroll
        for (int nf = 0; nf < 4; nf++) {
            int c0 = warpCol + nf * 8 + 2 * tg;
            __half2 p0 = __floats2half2_rn(acc[mf][nf][0], acc[mf][nf][1]);
            __half2 p1 = __floats2half2_rn(acc[mf][nf][2], acc[mf][nf][3]);
            *(uint32_t*)(Bh + r0 * HD + c0)       = *(uint32_t*)&p0;
            *(uint32_t*)(Bh + (r0 + 8) * HD + c0) = *(uint32_t*)&p1;
            acc[mf][nf][0] = __low2float(p0); acc[mf][nf][1] = __high2float(p0);
            acc[mf][nf][2] = __low2float(p1); acc[mf][nf][3] = __high2float(p1);
        }
    }

    __syncthreads();
    async_w_tile(aWH, aWL, WHA, WLA, 256, tid);        // Wx
    load_in_tile(inx, rowBase, sA, tid);
    asm volatile("cp.async.wait_group 0;" ::: "memory");
    __syncthreads();

    mma_block_hl(aSA, aWH, aWL, acc, warpRow, warpCol, L);

#pragma unroll
    for (int mf = 0; mf < 4; mf++) {
        size_t r0 = (size_t)rowBase + warpRow + mf * 16 + g;
#pragma unroll
        for (int nf = 0; nf < 4; nf++) {
            int c0 = warpCol + nf * 8 + 2 * tg;
            float b0 = sBias[c0], b1 = sBias[c0 + 1];
            __half2 p0 = __floats2half2_rn(acc[mf][nf][0] + b0, acc[mf][nf][1] + b1);
            __half2 p1 = __floats2half2_rn(acc[mf][nf][2] + b0, acc[mf][nf][3] + b1);
            *(uint32_t*)(Ah + r0 * HD + c0)       = *(uint32_t*)&p0;
            *(uint32_t*)(Ah + (r0 + 8) * HD + c0) = *(uint32_t*)&p1;
        }
    }
}

// ---------------- fused global_nn double GEMM ----------------
__global__ __launch_bounds__(THREADS, 2) void gemm_gg_kernel(
    const float* __restrict__ AGG,
    const __half* __restrict__ WH1, const __half* __restrict__ WL1,
    const __half* __restrict__ WH2, const __half* __restrict__ WL2,
    const float* __restrict__ gb1, const float* __restrict__ gb2,
    float* __restrict__ Out)
{
    extern __shared__ char sm[];
    float* sBias1 = (float*)sm;
    float* sBias2 = (float*)(sm + 512);
    uint32_t sb = smem_u32(sm);
    uint32_t aSA = sb + AB_SA;
    uint32_t aWH = sb + AB_WH, aWL = sb + AB_WL;
    uint32_t* sA = (uint32_t*)(sm + AB_SA);

    int tid = threadIdx.x, lane = tid & 31, wid = tid >> 5;
    int rowBase = blockIdx.x * 128;

    async_w_tile(aWH, aWL, WH1, WL1, HD, tid);

    if (tid < 128) { sBias1[tid] = gb1[tid]; sBias2[tid] = gb2[tid]; }
    load_in_tile(AGG, rowBase, sA, tid);

    asm volatile("cp.async.wait_group 0;" ::: "memory");
    __syncthreads();

    int warpRow = (wid & 1) * 64, warpCol = (wid >> 1) * 32;
    int g = lane >> 2, tg = lane & 3;
    LaneC L = lane_consts(lane);

    float acc[4][4][4];
#pragma unroll
    for (int i = 0; i < 4; i++)
#pragma unroll
        for (int j = 0; j < 4; j++)
#pragma unroll
            for (int q = 0; q < 4; q++) acc[i][j][q] = 0.f;

    mma_block_hl(aSA, aWH, aWL, acc, warpRow, warpCol, L);

    __syncthreads();
    async_w_tile(aWH, aWL, WH2, WL2, HD, tid);

#pragma unroll
    for (int mf = 0; mf < 4; mf++) {
        int r0 = warpRow + mf * 16 + g;
#pragma unroll
        for (int nf = 0; nf < 4; nf++) {
            int c0 = warpCol + nf * 8 + 2 * tg;
            float b0 = sBias1[c0], b1 = sBias1[c0 + 1];
            float o0 = fmaxf(acc[mf][nf][0] + b0, 0.f);
            float o1 = fmaxf(acc[mf][nf][1] + b1, 0.f);
            float o2 = fmaxf(acc[mf][nf][2] + b0, 0.f);
            float o3 = fmaxf(acc[mf][nf][3] + b1, 0.f);
            __half2 p0 = __floats2half2_rn(o0, o1);
            __half2 p1 = __floats2half2_rn(o2, o3);
            sA[r0 * TSH + (c0 >> 1)]       = *(uint32_t*)&p0;
            sA[(r0 + 8) * TSH + (c0 >> 1)] = *(uint32_t*)&p1;
            acc[mf][nf][0] = 0.f; acc[mf][nf][1] = 0.f;
            acc[mf][nf][2] = 0.f; acc[mf][nf][3] = 0.f;
        }
    }
    asm volatile("cp.async.wait_group 0;" ::: "memory");
    __syncthreads();

    mma_block_hl(aSA, aWH, aWL, acc, warpRow, warpCol, L);

#pragma unroll
    for (int mf = 0; mf < 4; mf++) {
        size_t r0 = (size_t)rowBase + warpRow + mf * 16 + g;
#pragma unroll
        for (int nf = 0; nf < 4; nf++) {
            int c0 = warpCol + nf * 8 + 2 * tg;
            float b0 = sBias2[c0], b1 = sBias2[c0 + 1];
            *(float2*)(Out + r0 * HD + c0) =
                make_float2(acc[mf][nf][0] + b0, acc[mf][nf][1] + b1);
            *(float2*)(Out + (r0 + 8) * HD + c0) =
                make_float2(acc[mf][nf][2] + b0, acc[mf][nf][3] + b1);
        }
    }
}

// ---------------- persistent edge kernel: smem B dedup ----------------
struct GReg {
    uint4 a[4], b[4];
    int d, r;
    bool valid;
};

// load A (always) and B (only when smem path disabled)
__device__ __forceinline__ void gather_issue(
    int eBase, int pass, GReg& G,
    const int* __restrict__ ssrc, const int* __restrict__ sdst,
    const __half* __restrict__ A, const __half* __restrict__ B,
    int total, int tid, bool loadB)
{
    int r = pass * 64 + (tid >> 2);
    int q = tid & 3;
    int e = eBase + r;
    G.valid = (e < total);
    int s = 0, d = 0;
    if (G.valid) { s = ssrc[e]; d = sdst[e]; }
    G.d = d; G.r = r;
    const uint4* Ar = (const uint4*)(A + (size_t)s * HD) + q * 4;
#pragma unroll
    for (int i = 0; i < 4; i++) G.a[i] = Ar[i];
    if (loadB) {
        const uint4* Br = (const uint4*)(B + (size_t)d * HD) + q * 4;
#pragma unroll
        for (int i = 0; i < 4; i++) G.b[i] = Br[i];
    }
}

__device__ __forceinline__ uint32_t hsubrelu(uint32_t a, uint32_t b) {
    __half2 r = __hmax2(__hsub2(*(__half2*)&a, *(__half2*)&b),
                        __float2half2_rn(0.f));
    return *(uint32_t*)&r;
}

// commit using B from registers (fallback / prologue)
__device__ __forceinline__ void gather_commit_g(
    const GReg& G, uint32_t* __restrict__ sTn, int* __restrict__ sDn, int tid)
{
    int q = tid & 3;
    if (q == 0) sDn[G.r] = G.valid ? G.d : -1;
    uint32_t* Tr = sTn + G.r * TSH + q * 16;
#pragma unroll
    for (int i = 0; i < 4; i++) {
        uint4 t;
        if (G.valid) {
            t.x = hsubrelu(G.a[i].x, G.b[i].x);
            t.y = hsubrelu(G.a[i].y, G.b[i].y);
            t.z = hsubrelu(G.a[i].z, G.b[i].z);
            t.w = hsubrelu(G.a[i].w, G.b[i].w);
        } else {
            t = make_uint4(0, 0, 0, 0);
        }
        *(uint4*)(Tr + i * 4) = t;
    }
}

// commit using B cached in smem (common path)
__device__ __forceinline__ void gather_commit_s(
    const GReg& G, const uint32_t* __restrict__ sB, int dmin,
    uint32_t* __restrict__ sTn, int* __restrict__ sDn, int tid)
{
    int q = tid & 3;
    if (q == 0) sDn[G.r] = G.valid ? G.d : -1;
    int bidx = G.valid ? (G.d - dmin) : 0;
    const uint4* Br = (const uint4*)(sB + bidx * TSH + q * 16);
    uint32_t* Tr = sTn + G.r * TSH + q * 16;
#pragma unroll
    for (int i = 0; i < 4; i++) {
        uint4 t;
        if (G.valid) {
            uint4 b = Br[i];
            t.x = hsubrelu(G.a[i].x, b.x);
            t.y = hsubrelu(G.a[i].y, b.y);
            t.z = hsubrelu(G.a[i].z, b.z);
            t.w = hsubrelu(G.a[i].w, b.w);
        } else {
            t = make_uint4(0, 0, 0, 0);
        }
        *(uint4*)(Tr + i * 4) = t;
    }
}

__device__ __forceinline__ void mma_half(
    uint32_t aST, uint32_t aSW,
    int ks0, float acc[4][4][4], int rowBase, int colBase, const LaneC& L)
{
#pragma unroll
    for (int ks = 0; ks < 4; ks++) {
        int base = (ks0 + ks) * 8;
        uint32_t b[4][2];
#pragma unroll
        for (int p = 0; p < 2; p++) {
            uint32_t r[4];
            uint32_t off = (uint32_t)(((colBase + p * 16 + L.rB) * TSH + base + L.kB) * 4);
            ldsm_x4(aSW + off, r);
            b[2*p][0] = r[0]; b[2*p][1] = r[1];
            b[2*p+1][0] = r[2]; b[2*p+1][1] = r[3];
        }
        uint32_t a[4][4];
#pragma unroll
        for (int mf = 0; mf < 4; mf++) {
            uint32_t off = (uint32_t)(((rowBase + mf * 16 + L.rA) * TSH + base + L.kA) * 4);
            ldsm_x4(aST + off, a[mf]);
        }
#pragma unroll
        for (int mf = 0; mf < 4; mf++)
#pragma unroll
            for (int nf = 0; nf < 4; nf++)
                mma_fp16(acc[mf][nf], a[mf], b[nf]);
    }
}

__device__ __forceinline__ void stage_frag_h(
    __half* __restrict__ sStage, float acc[4][4][4],
    int colBase, int g, int tg, const float* __restrict__ sBias)
{
#pragma unroll
    for (int mf = 0; mf < 4; mf++) {
        int r0 = mf * 16 + g;
#pragma unroll
        for (int nf = 0; nf < 4; nf++) {
            int c0 = colBase + nf * 8 + 2 * tg;
            float b0 = sBias[c0], b1 = sBias[c0 + 1];
            __half2 p0 = __floats2half2_rn(acc[mf][nf][0] + b0, acc[mf][nf][1] + b1);
            __half2 p1 = __floats2half2_rn(acc[mf][nf][2] + b0, acc[mf][nf][3] + b1);
            *(uint32_t*)(sStage + r0 * STGH + c0)       = *(uint32_t*)&p0;
            *(uint32_t*)(sStage + (r0 + 8) * STGH + c0) = *(uint32_t*)&p1;
        }
    }
}

__device__ __forceinline__ void scan_full(
    const __half* __restrict__ s0, const __half* __restrict__ s1,
    const int* __restrict__ sDst, float* __restrict__ agg, int tid)
{
    int c = tid & 127;
    int h = tid >> 7;
    const __half* buf = h ? s1 : s0;
    int gbase = h * 64;
    int prev = sDst[gbase];
    float m = -FLT_MAX;
    for (int r = 0; r < 64; r++) {
        int d = sDst[gbase + r];
        if (d != prev) {
            if (prev >= 0) atomic_fmax(agg + (size_t)prev * HD + c, m);
            m = -FLT_MAX;
            prev = d;
        }
        m = fmaxf(m, __half2float(buf[r * STGH + c]));
    }
    if (prev >= 0) atomic_fmax(agg + (size_t)prev * HD + c, m);
}

__global__ __launch_bounds__(THREADS, 2) void edge_mma_kernel(
    const int* __restrict__ ssrc, const int* __restrict__ sdst,
    const __half* __restrict__ A, const __half* __restrict__ B,
    const __half* __restrict__ W2T, const float* __restrict__ b2,
    float* __restrict__ agg, int total)
{
    extern __shared__ char smem[];
    int* sDst0 = (int*)smem;
    int* sDst1 = (int*)(smem + 512);
    float* sBias = (float*)(smem + 1024);
    uint32_t* sT = (uint32_t*)(smem + SM_T);
    __half* sStg0 = (__half*)(smem + SM_STG0);
    __half* sStg1 = (__half*)(smem + SM_STG1);
    uint32_t* sB = (uint32_t*)(smem + SM_B);

    uint32_t sb = smem_u32(smem);
    uint32_t aT = sb + SM_T, aW = sb + SM_W, aB = sb + SM_B;

    int tid = threadIdx.x;
    int lane = tid & 31, wid = tid >> 5;
    int ntiles = (total + 127) >> 7;

    // One-time: stream W2T (fp16, 32KB) into sW rows
    {
#pragma unroll
        for (int it = 0; it < 8; it++) {
            int linear = tid + it * THREADS;
            int n = linear >> 4, c = linear & 15;
            uint32_t dst = aW + (uint32_t)(n * (TSH * 4) + c * 16);
            const char* src = (const char*)W2T + n * 256 + c * 16;
            asm volatile("cp.async.cg.shared.global [%0], [%1], 16;"
                         :: "r"(dst), "l"(src));
        }
        asm volatile("cp.async.commit_group;" ::: "memory");
    }
    if (tid < 128) sBias[tid] = b2[tid];

    // Prologue: gather first tile (global-B path)
    if (blockIdx.x < ntiles) {
        GReg G;
        gather_issue(blockIdx.x * 128, 0, G, ssrc, sdst, A, B, total, tid, true);
        gather_commit_g(G, sT, sDst0, tid);
        gather_issue(blockIdx.x * 128, 1, G, ssrc, sdst, A, B, total, tid, true);
        gather_commit_g(G, sT, sDst0, tid);
    }
    asm volatile("cp.async.wait_group 0;" ::: "memory");
    __syncthreads();

    int rowBase = (wid & 1) * 64;
    int colBase = (wid >> 1) * 32;
    int g = lane >> 2, tg = lane & 3;
    LaneC L = lane_consts(lane);

    int* sDc = sDst0;
    int* sDn = sDst1;
    __half* myStg = rowBase ? sStg1 : sStg0;

    for (int ti = blockIdx.x; ti < ntiles; ti += GRID_EDGE) {
        int tn = ti + GRID_EDGE;
        bool hn = tn < ntiles;

        // Prefetch next tile's B rows into sB (dst range is contiguous,
        // avg ~8 rows). cp.async overlaps the MMA below. Fallback to
        // per-row global loads if the range exceeds BMAX (essentially never).
        int dmin = 0;
        bool useS = false;
        if (hn) {
            int eB = tn * 128;
            int last = min(eB + 127, total - 1);
            dmin = sdst[eB];                  // uniform across CTA
            int nrows = sdst[last] - dmin + 1;
            useS = (nrows <= BMAX);
            if (useS) {
                int nchunks = nrows * 16;     // 16B chunks per 256B row
                for (int ch = tid; ch < nchunks; ch += THREADS) {
                    int row = ch >> 4, c = ch & 15;
                    uint32_t dst = aB + (uint32_t)(row * (TSH * 4) + c * 16);
                    const char* src = (const char*)(B + (size_t)(dmin + row) * HD) + c * 16;
                    asm volatile("cp.async.cg.shared.global [%0], [%1], 16;"
                                 :: "r"(dst), "l"(src));
                }
                asm volatile("cp.async.commit_group;" ::: "memory");
            }
        }

        float acc[4][4][4];
#pragma unroll
        for (int i = 0; i < 4; i++)
#pragma unroll
            for (int j = 0; j < 4; j++)
#pragma unroll
                for (int q = 0; q < 4; q++) acc[i][j][q] = 0.f;

        mma_half(aT, aW, 0, acc, rowBase, colBase, L);
        mma_half(aT, aW, 4, acc, rowBase, colBase, L);

        GReg G;
        if (hn) gather_issue(tn * 128, 0, G, ssrc, sdst, A, B, total, tid, !useS);

        asm volatile("cp.async.wait_group 0;" ::: "memory");
        __syncthreads();   // S1: MMA reads of sT done; sB filled & visible

        if (hn) {
            if (useS) gather_commit_s(G, sB, dmin, sT, sDn, tid);
            else      gather_commit_g(G, sT, sDn, tid);
        }
        stage_frag_h(myStg, acc, colBase, g, tg, sBias);
        if (hn) gather_issue(tn * 128, 1, G, ssrc, sdst, A, B, total, tid, !useS);

        __syncthreads();   // S2: stages visible

        scan_full(sStg0, sStg1, sDc, agg, tid);
        if (hn) {
            if (useS) gather_commit_s(G, sB, dmin, sT, sDn, tid);
            else      gather_commit_g(G, sT, sDn, tid);
        }

        __syncthreads();   // S3: scan + commits done

        int* tmp = sDc; sDc = sDn; sDn = tmp;
    }
}

// ---------------- launch ----------------
extern "C" void kernel_launch(void* const* d_in, const int* in_sizes, int n_in,
                              void* d_out, int out_size)
{
    (void)n_in; (void)out_size;
    const float* x   = (const float*)d_in[0];
    const float* pos = (const float*)d_in[1];
    const int* ei    = (const int*)d_in[2];
    const float* p[16];
    for (int i = 0; i < 16; i++) p[i] = (const float*)d_in[3 + i];

    int E = in_sizes[2] / 2;
    int total = E + NODES;

    float *AGG, *H0;
    __half *AH, *BH, *W2T, *WHA, *WLA, *WH1, *WL1, *WH2, *WL2;
    int *CNT, *NEXT, *SSRC, *SDST;
    cudaGetSymbolAddress((void**)&AH, g_Ah);
    cudaGetSymbolAddress((void**)&BH, g_Bh);
    cudaGetSymbolAddress((void**)&AGG, g_agg);
    cudaGetSymbolAddress((void**)&H0, g_h0);
    cudaGetSymbolAddress((void**)&W2T, g_w2t);
    cudaGetSymbolAddress((void**)&WHA, g_whA);
    cudaGetSymbolAddress((void**)&WLA, g_wlA);
    cudaGetSymbolAddress((void**)&WH1, g_wh1);
    cudaGetSymbolAddress((void**)&WL1, g_wl1);
    cudaGetSymbolAddress((void**)&WH2, g_wh2);
    cudaGetSymbolAddress((void**)&WL2, g_wl2);
    cudaGetSymbolAddress((void**)&CNT, g_cnt);
    cudaGetSymbolAddress((void**)&NEXT, g_next);
    cudaGetSymbolAddress((void**)&SSRC, g_ssrc);
    cudaGetSymbolAddress((void**)&SDST, g_sdst);

    cudaFuncSetAttribute(edge_mma_kernel, cudaFuncAttributeMaxDynamicSharedMemorySize, EDGE_SMEM);
    cudaFuncSetAttribute(gemm_ab_kernel, cudaFuncAttributeMaxDynamicSharedMemorySize, AB_SMEM);
    cudaFuncSetAttribute(gemm_gg_kernel, cudaFuncAttributeMaxDynamicSharedMemorySize, AB_SMEM);

    int gemmBlocks = NODES / 128;              // 512
    int fillBlocks = (NODES * HD / 4 + THREADS - 1) / THREADS;
    int eBlocks = (total + THREADS - 1) / THREADS;

    // Build dst-sorted edge list once (layer-invariant)
    zero_i32<<<(NODES + THREADS - 1) / THREADS, THREADS>>>(CNT, NODES);
    hist_kernel<<<eBlocks, THREADS>>>(ei, CNT, E, total);
    scan_kernel<<<1, SCAN_T>>>(CNT, NEXT);
    scatter_kernel<<<eBlocks, THREADS>>>(ei, NEXT, SSRC, SDST, E, total);

    for (int layer = 0; layer < 2; layer++) {
        const float* lw1 = p[layer * 8 + 0];
        const float* lb1 = p[layer * 8 + 1];
        const float* lw2 = p[layer * 8 + 2];
        const float* lb2 = p[layer * 8 + 3];
        const float* gw1 = p[layer * 8 + 4];
        const float* gb1 = p[layer * 8 + 5];
        const float* gw2 = p[layer * 8 + 6];
        const float* gb2 = p[layer * 8 + 7];
        const float* inx = (layer == 0) ? x : H0;
        float* outp = (layer == 0) ? H0 : (float*)d_out;

        prep_all_kernel<<<640, HD>>>(lw1, lw2, gw1, gw2,
                                     WHA, WLA, W2T, WH1, WL1, WH2, WL2);

        gemm_ab_kernel<<<gemmBlocks, THREADS, AB_SMEM>>>(
            pos, inx, WHA, WLA, lb1, AH, BH);

        fill_kernel<<<fillBlocks, THREADS>>>((float4*)AGG, -FLT_MAX, NODES * HD / 4);
        edge_mma_kernel<<<GRID_EDGE, THREADS, EDGE_SMEM>>>(
            SSRC, SDST, AH, BH, W2T, lb2, AGG, total);

        gemm_gg_kernel<<<gemmBlocks, THREADS, AB_SMEM>>>(
            AGG, WH1, WL1, WH2, WL2, gb1, gb2, outp);
    }
}

// round 17
// speedup vs baseline: 1.0194x; 1.0194x over previous
#include <cuda_runtime.h>
#include <cuda_fp16.h>
#include <float.h>
#include <stdint.h>

#define NODES 65536
#define HD 128
#define THREADS 256
#define TSH 68                       // uint32 (half2) stride per 128-half row
#define STGH 132                     // fp16 staging stride (halves)
#define MAXEDGES (1048576 + NODES)
#define GRID_EDGE 304

// edge kernel smem map (bytes)
#define HBUF (128 * TSH * 4)         // 34816
#define SM_T 2048
#define SM_W (2048 + HBUF)
#define STG_BYTES (64 * STGH * 2)    // 16896
#define SM_STG0 (2048 + 2 * HBUF)
#define SM_STG1 (SM_STG0 + STG_BYTES)
#define EDGE_SMEM (SM_STG0 + 2 * STG_BYTES)   // 105472 -> 2 CTAs/SM

// node GEMM smem: header(1024) + sA + WH + WL   -> 2 CTAs/SM
#define AB_SA 1024
#define AB_WH (1024 + HBUF)
#define AB_WL (1024 + 2 * HBUF)
#define AB_SMEM (1024 + 3 * HBUF)    // 105472

// ---------------- scratch ----------------
__device__ __half g_Ah[(size_t)NODES * HD];
__device__ __half g_Bh[(size_t)NODES * HD];
__device__ float g_agg[(size_t)NODES * HD];
__device__ float g_h0[(size_t)NODES * HD];
__device__ __half g_w2t[HD * HD];
__device__ __half g_whA[HD * 256];
__device__ __half g_wlA[HD * 256];
__device__ __half g_wh1[HD * HD];
__device__ __half g_wl1[HD * HD];
__device__ __half g_wh2[HD * HD];
__device__ __half g_wl2[HD * HD];
__device__ int g_cnt[NODES];
__device__ int g_next[NODES];
__device__ int g_ssrc[MAXEDGES];
__device__ int g_sdst[MAXEDGES];

__global__ __launch_bounds__(THREADS) void fill_kernel(float4* p, float v, int n4) {
    int i = blockIdx.x * blockDim.x + threadIdx.x;
    if (i < n4) p[i] = make_float4(v, v, v, v);
}

__global__ __launch_bounds__(THREADS) void zero_i32(int* p, int n) {
    int i = blockIdx.x * blockDim.x + threadIdx.x;
    if (i < n) p[i] = 0;
}

// ---------------- counting sort by dst (once per launch) ----------------
__global__ __launch_bounds__(THREADS) void hist_kernel(
    const int* __restrict__ ei, int* __restrict__ cnt, int E, int total)
{
    int e = blockIdx.x * blockDim.x + threadIdx.x;
    if (e < total) {
        int d = (e < E) ? ei[E + e] : (e - E);
        atomicAdd(&cnt[d], 1);
    }
}

#define SCAN_T 1024
#define CHUNK (NODES / SCAN_T)   // 64
__global__ __launch_bounds__(SCAN_T) void scan_kernel(
    const int* __restrict__ cnt, int* __restrict__ next)
{
    __shared__ int part[SCAN_T];
    int t = threadIdx.x;
    int base = t * CHUNK;
    int sum = 0;
#pragma unroll 4
    for (int i = 0; i < CHUNK; i++) sum += cnt[base + i];
    part[t] = sum;
    __syncthreads();
    for (int off = 1; off < SCAN_T; off <<= 1) {
        int v = (t >= off) ? part[t - off] : 0;
        __syncthreads();
        part[t] += v;
        __syncthreads();
    }
    int off = part[t] - sum;   // exclusive
#pragma unroll 4
    for (int i = 0; i < CHUNK; i++) {
        next[base + i] = off;
        off += cnt[base + i];
    }
}

__global__ __launch_bounds__(THREADS) void scatter_kernel(
    const int* __restrict__ ei, int* __restrict__ next,
    int* __restrict__ ssrc, int* __restrict__ sdst, int E, int total)
{
    int e = blockIdx.x * blockDim.x + threadIdx.x;
    if (e < total) {
        int s, d;
        if (e < E) { s = ei[e]; d = ei[E + e]; }
        else       { s = e - E; d = s; }
        int pos = atomicAdd(&next[d], 1);
        ssrc[pos] = s;
        sdst[pos] = d;
    }
}

// ---------------- unified weight prep ----------------
__global__ __launch_bounds__(HD) void prep_all_kernel(
    const float* __restrict__ lw1, const float* __restrict__ lw2,
    const float* __restrict__ gw1, const float* __restrict__ gw2,
    __half* __restrict__ whA, __half* __restrict__ wlA,
    __half* __restrict__ w2t,
    __half* __restrict__ wh1, __half* __restrict__ wl1,
    __half* __restrict__ wh2, __half* __restrict__ wl2)
{
    int b = blockIdx.x, n = threadIdx.x;
    if (b < 256) {
        int k = b;
        float v = lw1[k * HD + n];
        __half h = __float2half_rn(v);
        whA[n * 256 + k] = h;
        wlA[n * 256 + k] = __float2half_rn(v - __half2float(h));
    } else if (b < 384) {
        int nn = b - 256;
        w2t[nn * HD + n] = __float2half(lw2[n * HD + nn]);
    } else if (b < 512) {
        int k = b - 384;
        float v = gw1[k * HD + n];
        __half h = __float2half_rn(v);
        wh1[n * HD + k] = h;
        wl1[n * HD + k] = __float2half_rn(v - __half2float(h));
    } else {
        int k = b - 512;
        float v = gw2[k * HD + n];
        __half h = __float2half_rn(v);
        wh2[n * HD + k] = h;
        wl2[n * HD + k] = __float2half_rn(v - __half2float(h));
    }
}

// ---------------- mma / ldmatrix helpers ----------------
__device__ __forceinline__ void mma_fp16(float* d, const uint32_t* a, const uint32_t* b) {
    asm volatile(
        "mma.sync.aligned.m16n8k16.row.col.f32.f16.f16.f32 "
        "{%0,%1,%2,%3}, {%4,%5,%6,%7}, {%8,%9}, {%0,%1,%2,%3};"
        : "+f"(d[0]), "+f"(d[1]), "+f"(d[2]), "+f"(d[3])
        : "r"(a[0]), "r"(a[1]), "r"(a[2]), "r"(a[3]), "r"(b[0]), "r"(b[1]));
}

__device__ __forceinline__ void ldsm_x4(uint32_t addr, uint32_t* r) {
    asm volatile(
        "ldmatrix.sync.aligned.m8n8.x4.shared.b16 {%0,%1,%2,%3}, [%4];"
        : "=r"(r[0]), "=r"(r[1]), "=r"(r[2]), "=r"(r[3]) : "r"(addr));
}

__device__ __forceinline__ void atomic_fmax(float* p, float v) {
    if (v >= 0.f) atomicMax((int*)p, __float_as_int(v));
    else          atomicMin((unsigned int*)p, __float_as_uint(v));
}

__device__ __forceinline__ uint32_t smem_u32(const void* p) {
    uint32_t a;
    asm("{ .reg .u64 t; cvta.to.shared.u64 t, %1; cvt.u32.u64 %0, t; }"
        : "=r"(a) : "l"(p));
    return a;
}

struct LaneC { int rA, kA, rB, kB; };
__device__ __forceinline__ LaneC lane_consts(int lane) {
    LaneC c;
    c.rA = lane & 15;
    c.kA = (lane >> 4) * 4;
    c.rB = (lane & 7) + ((lane >> 4) << 3);
    c.kB = ((lane >> 3) & 1) * 4;
    return c;
}

// 8-kstep MMA block with hi/lo split weights (node GEMMs)
__device__ __forceinline__ void mma_block_hl(
    uint32_t aSA, uint32_t aWH, uint32_t aWL,
    float acc[4][4][4], int warpRow, int warpCol, const LaneC& L)
{
#pragma unroll
    for (int ks = 0; ks < 8; ks++) {
        int base = ks * 8;
        uint32_t bh[4][2], bl[4][2];
#pragma unroll
        for (int p = 0; p < 2; p++) {
            uint32_t r[4];
            uint32_t off = (uint32_t)(((warpCol + p * 16 + L.rB) * TSH + base + L.kB) * 4);
            ldsm_x4(aWH + off, r);
            bh[2*p][0] = r[0]; bh[2*p][1] = r[1];
            bh[2*p+1][0] = r[2]; bh[2*p+1][1] = r[3];
            ldsm_x4(aWL + off, r);
            bl[2*p][0] = r[0]; bl[2*p][1] = r[1];
            bl[2*p+1][0] = r[2]; bl[2*p+1][1] = r[3];
        }
        uint32_t a[4][4];
#pragma unroll
        for (int mf = 0; mf < 4; mf++) {
            uint32_t off = (uint32_t)(((warpRow + mf * 16 + L.rA) * TSH + base + L.kA) * 4);
            ldsm_x4(aSA + off, a[mf]);
        }
#pragma unroll
        for (int mf = 0; mf < 4; mf++)
#pragma unroll
            for (int nf = 0; nf < 4; nf++) {
                mma_fp16(acc[mf][nf], a[mf], bh[nf]);
                mma_fp16(acc[mf][nf], a[mf], bl[nf]);
            }
    }
}

__device__ __forceinline__ void async_w_tile(
    uint32_t dstH, uint32_t dstL,
    const __half* __restrict__ srcH, const __half* __restrict__ srcL,
    int srcStride, int tid)
{
#pragma unroll
    for (int it = 0; it < 8; it++) {
        int lin = tid + it * THREADS;
        int n = lin >> 4, c = lin & 15;
        uint32_t off = (uint32_t)(n * (TSH * 4) + c * 16);
        asm volatile("cp.async.cg.shared.global [%0], [%1], 16;"
                     :: "r"(dstH + off), "l"(srcH + (size_t)n * srcStride + c * 8));
        asm volatile("cp.async.cg.shared.global [%0], [%1], 16;"
                     :: "r"(dstL + off), "l"(srcL + (size_t)n * srcStride + c * 8));
    }
    asm volatile("cp.async.commit_group;" ::: "memory");
}

__device__ __forceinline__ void load_in_tile(
    const float* __restrict__ In, int rowBase, uint32_t* sA, int tid)
{
    int r = tid >> 1, h = tid & 1;
    const float4* src = (const float4*)(In + (size_t)(rowBase + r) * HD + h * 64);
    uint32_t* dst = sA + r * TSH + h * 32;
#pragma unroll
    for (int j = 0; j < 8; j++) {
        float4 v0 = src[j * 2], v1 = src[j * 2 + 1];
        __half2 a = __floats2half2_rn(v0.x, v0.y);
        __half2 b = __floats2half2_rn(v0.z, v0.w);
        __half2 c = __floats2half2_rn(v1.x, v1.y);
        __half2 d = __floats2half2_rn(v1.z, v1.w);
        uint4 u = make_uint4(*(uint32_t*)&a, *(uint32_t*)&b,
                             *(uint32_t*)&c, *(uint32_t*)&d);
        *(uint4*)(dst + j * 4) = u;
    }
}

// ---------------- fused A/B node GEMM (2 CTAs/SM, sequential W) ----------------
__global__ __launch_bounds__(THREADS, 2) void gemm_ab_kernel(
    const float* __restrict__ pos, const float* __restrict__ inx,
    const __half* __restrict__ WHA, const __half* __restrict__ WLA,
    const float* __restrict__ lb1,
    __half* __restrict__ Ah, __half* __restrict__ Bh)
{
    extern __shared__ char sm[];
    float* sBias = (float*)sm;
    uint32_t sb = smem_u32(sm);
    uint32_t aSA = sb + AB_SA;
    uint32_t aWH = sb + AB_WH, aWL = sb + AB_WL;
    uint32_t* sA = (uint32_t*)(sm + AB_SA);

    int tid = threadIdx.x, lane = tid & 31, wid = tid >> 5;
    int rowBase = blockIdx.x * 128;

    async_w_tile(aWH, aWL, WHA + 128, WLA + 128, 256, tid);   // Wp

    if (tid < 128) sBias[tid] = lb1[tid];
    load_in_tile(pos, rowBase, sA, tid);

    asm volatile("cp.async.wait_group 0;" ::: "memory");
    __syncthreads();

    int warpRow = (wid & 1) * 64, warpCol = (wid >> 1) * 32;
    int g = lane >> 2, tg = lane & 3;
    LaneC L = lane_consts(lane);

    float acc[4][4][4];
#pragma unroll
    for (int i = 0; i < 4; i++)
#pragma unroll
        for (int j = 0; j < 4; j++)
#pragma unroll
            for (int q = 0; q < 4; q++) acc[i][j][q] = 0.f;

    mma_block_hl(aSA, aWH, aWL, acc, warpRow, warpCol, L);

#pragma unroll
    for (int mf = 0; mf < 4; mf++) {
        size_t r0 = (size_t)rowBase + warpRow + mf * 16 + g;
#pragma unroll
        for (int nf = 0; nf < 4; nf++) {
            int c0 = warpCol + nf * 8 + 2 * tg;
            __half2 p0 = __floats2half2_rn(acc[mf][nf][0], acc[mf][nf][1]);
            __half2 p1 = __floats2half2_rn(acc[mf][nf][2], acc[mf][nf][3]);
            *(uint32_t*)(Bh + r0 * HD + c0)       = *(uint32_t*)&p0;
            *(uint32_t*)(Bh + (r0 + 8) * HD + c0) = *(uint32_t*)&p1;
            acc[mf][nf][0] = __low2float(p0); acc[mf][nf][1] = __high2float(p0);
            acc[mf][nf][2] = __low2float(p1); acc[mf][nf][3] = __high2float(p1);
        }
    }

    __syncthreads();
    async_w_tile(aWH, aWL, WHA, WLA, 256, tid);        // Wx
    load_in_tile(inx, rowBase, sA, tid);
    asm volatile("cp.async.wait_group 0;" ::: "memory");
    __syncthreads();

    mma_block_hl(aSA, aWH, aWL, acc, warpRow, warpCol, L);

#pragma unroll
    for (int mf = 0; mf < 4; mf++) {
        size_t r0 = (size_t)rowBase + warpRow + mf * 16 + g;
#pragma unroll
        for (int nf = 0; nf < 4; nf++) {
            int c0 = warpCol + nf * 8 + 2 * tg;
            float b0 = sBias[c0], b1 = sBias[c0 + 1];
            __half2 p0 = __floats2half2_rn(acc[mf][nf][0] + b0, acc[mf][nf][1] + b1);
            __half2 p1 = __floats2half2_rn(acc[mf][nf][2] + b0, acc[mf][nf][3] + b1);
            *(uint32_t*)(Ah + r0 * HD + c0)       = *(uint32_t*)&p0;
            *(uint32_t*)(Ah + (r0 + 8) * HD + c0) = *(uint32_t*)&p1;
        }
    }
}

// ---------------- fused global_nn double GEMM ----------------
__global__ __launch_bounds__(THREADS, 2) void gemm_gg_kernel(
    const float* __restrict__ AGG,
    const __half* __restrict__ WH1, const __half* __restrict__ WL1,
    const __half* __restrict__ WH2, const __half* __restrict__ WL2,
    const float* __restrict__ gb1, const float* __restrict__ gb2,
    float* __restrict__ Out)
{
    extern __shared__ char sm[];
    float* sBias1 = (float*)sm;
    float* sBias2 = (float*)(sm + 512);
    uint32_t sb = smem_u32(sm);
    uint32_t aSA = sb + AB_SA;
    uint32_t aWH = sb + AB_WH, aWL = sb + AB_WL;
    uint32_t* sA = (uint32_t*)(sm + AB_SA);

    int tid = threadIdx.x, lane = tid & 31, wid = tid >> 5;
    int rowBase = blockIdx.x * 128;

    async_w_tile(aWH, aWL, WH1, WL1, HD, tid);

    if (tid < 128) { sBias1[tid] = gb1[tid]; sBias2[tid] = gb2[tid]; }
    load_in_tile(AGG, rowBase, sA, tid);

    asm volatile("cp.async.wait_group 0;" ::: "memory");
    __syncthreads();

    int warpRow = (wid & 1) * 64, warpCol = (wid >> 1) * 32;
    int g = lane >> 2, tg = lane & 3;
    LaneC L = lane_consts(lane);

    float acc[4][4][4];
#pragma unroll
    for (int i = 0; i < 4; i++)
#pragma unroll
        for (int j = 0; j < 4; j++)
#pragma unroll
            for (int q = 0; q < 4; q++) acc[i][j][q] = 0.f;

    mma_block_hl(aSA, aWH, aWL, acc, warpRow, warpCol, L);

    __syncthreads();
    async_w_tile(aWH, aWL, WH2, WL2, HD, tid);

#pragma unroll
    for (int mf = 0; mf < 4; mf++) {
        int r0 = warpRow + mf * 16 + g;
#pragma unroll
        for (int nf = 0; nf < 4; nf++) {
            int c0 = warpCol + nf * 8 + 2 * tg;
            float b0 = sBias1[c0], b1 = sBias1[c0 + 1];
            float o0 = fmaxf(acc[mf][nf][0] + b0, 0.f);
            float o1 = fmaxf(acc[mf][nf][1] + b1, 0.f);
            float o2 = fmaxf(acc[mf][nf][2] + b0, 0.f);
            float o3 = fmaxf(acc[mf][nf][3] + b1, 0.f);
            __half2 p0 = __floats2half2_rn(o0, o1);
            __half2 p1 = __floats2half2_rn(o2, o3);
            sA[r0 * TSH + (c0 >> 1)]       = *(uint32_t*)&p0;
            sA[(r0 + 8) * TSH + (c0 >> 1)] = *(uint32_t*)&p1;
            acc[mf][nf][0] = 0.f; acc[mf][nf][1] = 0.f;
            acc[mf][nf][2] = 0.f; acc[mf][nf][3] = 0.f;
        }
    }
    asm volatile("cp.async.wait_group 0;" ::: "memory");
    __syncthreads();

    mma_block_hl(aSA, aWH, aWL, acc, warpRow, warpCol, L);

#pragma unroll
    for (int mf = 0; mf < 4; mf++) {
        size_t r0 = (size_t)rowBase + warpRow + mf * 16 + g;
#pragma unroll
        for (int nf = 0; nf < 4; nf++) {
            int c0 = warpCol + nf * 8 + 2 * tg;
            float b0 = sBias2[c0], b1 = sBias2[c0 + 1];
            *(float2*)(Out + r0 * HD + c0) =
                make_float2(acc[mf][nf][0] + b0, acc[mf][nf][1] + b1);
            *(float2*)(Out + (r0 + 8) * HD + c0) =
                make_float2(acc[mf][nf][2] + b0, acc[mf][nf][3] + b1);
        }
    }
}

// ---------------- persistent edge kernel: 2 CTAs/SM, fp16 dual staging ----------------
struct GReg {
    uint4 a[4], b[4];
    int d, r;
    bool valid;
};

__device__ __forceinline__ void gather_issue(
    int eBase, int pass, GReg& G,
    const int* __restrict__ ssrc, const int* __restrict__ sdst,
    const __half* __restrict__ A, const __half* __restrict__ B,
    int total, int tid)
{
    int r = pass * 64 + (tid >> 2);
    int q = tid & 3;
    int e = eBase + r;
    G.valid = (e < total);
    int s = 0, d = 0;
    if (G.valid) { s = ssrc[e]; d = sdst[e]; }
    G.d = d; G.r = r;
    const uint4* Ar = (const uint4*)(A + (size_t)s * HD) + q * 4;
    const uint4* Br = (const uint4*)(B + (size_t)d * HD) + q * 4;
#pragma unroll
    for (int i = 0; i < 4; i++) { G.a[i] = Ar[i]; G.b[i] = Br[i]; }
}

__device__ __forceinline__ uint32_t hsubrelu(uint32_t a, uint32_t b) {
    __half2 r = __hmax2(__hsub2(*(__half2*)&a, *(__half2*)&b),
                        __float2half2_rn(0.f));
    return *(uint32_t*)&r;
}

__device__ __forceinline__ void gather_commit(
    const GReg& G, uint32_t* __restrict__ sTn, int* __restrict__ sDn, int tid)
{
    int q = tid & 3;
    if (q == 0) sDn[G.r] = G.valid ? G.d : -1;
    uint32_t* Tr = sTn + G.r * TSH + q * 16;
#pragma unroll
    for (int i = 0; i < 4; i++) {
        uint4 t;
        if (G.valid) {
            t.x = hsubrelu(G.a[i].x, G.b[i].x);
            t.y = hsubrelu(G.a[i].y, G.b[i].y);
            t.z = hsubrelu(G.a[i].z, G.b[i].z);
            t.w = hsubrelu(G.a[i].w, G.b[i].w);
        } else {
            t = make_uint4(0, 0, 0, 0);
        }
        *(uint4*)(Tr + i * 4) = t;
    }
}

__device__ __forceinline__ void mma_half(
    uint32_t aST, uint32_t aSW,
    int ks0, float acc[4][4][4], int rowBase, int colBase, const LaneC& L)
{
#pragma unroll
    for (int ks = 0; ks < 4; ks++) {
        int base = (ks0 + ks) * 8;
        uint32_t b[4][2];
#pragma unroll
        for (int p = 0; p < 2; p++) {
            uint32_t r[4];
            uint32_t off = (uint32_t)(((colBase + p * 16 + L.rB) * TSH + base + L.kB) * 4);
            ldsm_x4(aSW + off, r);
            b[2*p][0] = r[0]; b[2*p][1] = r[1];
            b[2*p+1][0] = r[2]; b[2*p+1][1] = r[3];
        }
        uint32_t a[4][4];
#pragma unroll
        for (int mf = 0; mf < 4; mf++) {
            uint32_t off = (uint32_t)(((rowBase + mf * 16 + L.rA) * TSH + base + L.kA) * 4);
            ldsm_x4(aST + off, a[mf]);
        }
#pragma unroll
        for (int mf = 0; mf < 4; mf++)
#pragma unroll
            for (int nf = 0; nf < 4; nf++)
                mma_fp16(acc[mf][nf], a[mf], b[nf]);
    }
}

// stage warp's 64x32 block (local rows 0..63) + bias into fp16 buffer.
// fp16 rounding here is numerically identical to the downstream gemm_gg input
// conversion (rounding is monotonic, so max(round(x)) == round(max(x))).
__device__ __forceinline__ void stage_frag_h(
    __half* __restrict__ sStage, float acc[4][4][4],
    int colBase, int g, int tg, const float* __restrict__ sBias)
{
#pragma unroll
    for (int mf = 0; mf < 4; mf++) {
        int r0 = mf * 16 + g;
#pragma unroll
        for (int nf = 0; nf < 4; nf++) {
            int c0 = colBase + nf * 8 + 2 * tg;
            float b0 = sBias[c0], b1 = sBias[c0 + 1];
            __half2 p0 = __floats2half2_rn(acc[mf][nf][0] + b0, acc[mf][nf][1] + b1);
            __half2 p1 = __floats2half2_rn(acc[mf][nf][2] + b0, acc[mf][nf][3] + b1);
            *(uint32_t*)(sStage + r0 * STGH + c0)       = *(uint32_t*)&p0;
            *(uint32_t*)(sStage + (r0 + 8) * STGH + c0) = *(uint32_t*)&p1;
        }
    }
}

// full 128-row segmented column-max: 2 threads/col, 64 serial rows each
__device__ __forceinline__ void scan_full(
    const __half* __restrict__ s0, const __half* __restrict__ s1,
    const int* __restrict__ sDst, float* __restrict__ agg, int tid)
{
    int c = tid & 127;
    int h = tid >> 7;
    const __half* buf = h ? s1 : s0;
    int gbase = h * 64;
    int prev = sDst[gbase];
    float m = -FLT_MAX;
    for (int r = 0; r < 64; r++) {
        int d = sDst[gbase + r];
        if (d != prev) {
            if (prev >= 0) atomic_fmax(agg + (size_t)prev * HD + c, m);
            m = -FLT_MAX;
            prev = d;
        }
        m = fmaxf(m, __half2float(buf[r * STGH + c]));
    }
    if (prev >= 0) atomic_fmax(agg + (size_t)prev * HD + c, m);
}

__global__ __launch_bounds__(THREADS, 2) void edge_mma_kernel(
    const int* __restrict__ ssrc, const int* __restrict__ sdst,
    const __half* __restrict__ A, const __half* __restrict__ B,
    const __half* __restrict__ W2T, const float* __restrict__ b2,
    float* __restrict__ agg, int total)
{
    extern __shared__ char smem[];
    int* sDst0 = (int*)smem;
    int* sDst1 = (int*)(smem + 512);
    float* sBias = (float*)(smem + 1024);
    uint32_t* sT = (uint32_t*)(smem + SM_T);
    __half* sStg0 = (__half*)(smem + SM_STG0);
    __half* sStg1 = (__half*)(smem + SM_STG1);

    uint32_t sb = smem_u32(smem);
    uint32_t aT = sb + SM_T, aW = sb + SM_W;

    int tid = threadIdx.x;
    int lane = tid & 31, wid = tid >> 5;
    int ntiles = (total + 127) >> 7;

    // One-time: stream W2T (fp16, 32KB) into sW rows
    {
#pragma unroll
        for (int it = 0; it < 8; it++) {
            int linear = tid + it * THREADS;
            int n = linear >> 4, c = linear & 15;
            uint32_t dst = aW + (uint32_t)(n * (TSH * 4) + c * 16);
            const char* src = (const char*)W2T + n * 256 + c * 16;
            asm volatile("cp.async.cg.shared.global [%0], [%1], 16;"
                         :: "r"(dst), "l"(src));
        }
        asm volatile("cp.async.commit_group;" ::: "memory");
    }
    if (tid < 128) sBias[tid] = b2[tid];

    // Prologue: gather first tile into sT / sDst0
    if (blockIdx.x < ntiles) {
        GReg G;
        gather_issue(blockIdx.x * 128, 0, G, ssrc, sdst, A, B, total, tid);
        gather_commit(G, sT, sDst0, tid);
        gather_issue(blockIdx.x * 128, 1, G, ssrc, sdst, A, B, total, tid);
        gather_commit(G, sT, sDst0, tid);
    }
    asm volatile("cp.async.wait_group 0;" ::: "memory");
    __syncthreads();

    int rowBase = (wid & 1) * 64;
    int colBase = (wid >> 1) * 32;
    int g = lane >> 2, tg = lane & 3;
    LaneC L = lane_consts(lane);

    int* sDc = sDst0;
    int* sDn = sDst1;
    __half* myStg = rowBase ? sStg1 : sStg0;

    for (int ti = blockIdx.x; ti < ntiles; ti += GRID_EDGE) {
        int tn = ti + GRID_EDGE;
        bool hn = tn < ntiles;

        float acc[4][4][4];
#pragma unroll
        for (int i = 0; i < 4; i++)
#pragma unroll
            for (int j = 0; j < 4; j++)
#pragma unroll
                for (int q = 0; q < 4; q++) acc[i][j][q] = 0.f;

        mma_half(aT, aW, 0, acc, rowBase, colBase, L);

        GReg G;
        if (hn) gather_issue(tn * 128, 0, G, ssrc, sdst, A, B, total, tid);

        mma_half(aT, aW, 4, acc, rowBase, colBase, L);

        __syncthreads();   // S1: MMA reads of sT done (also orders prev scan)

        if (hn) gather_commit(G, sT, sDn, tid);          // next rows 0..63
        stage_frag_h(myStg, acc, colBase, g, tg, sBias); // both halves concurrently
        if (hn) gather_issue(tn * 128, 1, G, ssrc, sdst, A, B, total, tid);

        __syncthreads();   // S2: stages visible

        scan_full(sStg0, sStg1, sDc, agg, tid);
        if (hn) gather_commit(G, sT, sDn, tid);          // rows 64..127, overlaps scan

        __syncthreads();   // S3: scan done (bufs free), commits done

        int* tmp = sDc; sDc = sDn; sDn = tmp;
    }
}

// ---------------- launch ----------------
extern "C" void kernel_launch(void* const* d_in, const int* in_sizes, int n_in,
                              void* d_out, int out_size)
{
    (void)n_in; (void)out_size;
    const float* x   = (const float*)d_in[0];
    const float* pos = (const float*)d_in[1];
    const int* ei    = (const int*)d_in[2];
    const float* p[16];
    for (int i = 0; i < 16; i++) p[i] = (const float*)d_in[3 + i];

    int E = in_sizes[2] / 2;
    int total = E + NODES;

    float *AGG, *H0;
    __half *AH, *BH, *W2T, *WHA, *WLA, *WH1, *WL1, *WH2, *WL2;
    int *CNT, *NEXT, *SSRC, *SDST;
    cudaGetSymbolAddress((void**)&AH, g_Ah);
    cudaGetSymbolAddress((void**)&BH, g_Bh);
    cudaGetSymbolAddress((void**)&AGG, g_agg);
    cudaGetSymbolAddress((void**)&H0, g_h0);
    cudaGetSymbolAddress((void**)&W2T, g_w2t);
    cudaGetSymbolAddress((void**)&WHA, g_whA);
    cudaGetSymbolAddress((void**)&WLA, g_wlA);
    cudaGetSymbolAddress((void**)&WH1, g_wh1);
    cudaGetSymbolAddress((void**)&WL1, g_wl1);
    cudaGetSymbolAddress((void**)&WH2, g_wh2);
    cudaGetSymbolAddress((void**)&WL2, g_wl2);
    cudaGetSymbolAddress((void**)&CNT, g_cnt);
    cudaGetSymbolAddress((void**)&NEXT, g_next);
    cudaGetSymbolAddress((void**)&SSRC, g_ssrc);
    cudaGetSymbolAddress((void**)&SDST, g_sdst);

    cudaFuncSetAttribute(edge_mma_kernel, cudaFuncAttributeMaxDynamicSharedMemorySize, EDGE_SMEM);
    cudaFuncSetAttribute(gemm_ab_kernel, cudaFuncAttributeMaxDynamicSharedMemorySize, AB_SMEM);
    cudaFuncSetAttribute(gemm_gg_kernel, cudaFuncAttributeMaxDynamicSharedMemorySize, AB_SMEM);

    int gemmBlocks = NODES / 128;              // 512
    int fillBlocks = (NODES * HD / 4 + THREADS - 1) / THREADS;
    int eBlocks = (total + THREADS - 1) / THREADS;

    // Build dst-sorted edge list once (layer-invariant)
    zero_i32<<<(NODES + THREADS - 1) / THREADS, THREADS>>>(CNT, NODES);
    hist_kernel<<<eBlocks, THREADS>>>(ei, CNT, E, total);
    scan_kernel<<<1, SCAN_T>>>(CNT, NEXT);
    scatter_kernel<<<eBlocks, THREADS>>>(ei, NEXT, SSRC, SDST, E, total);

    for (int layer = 0; layer < 2; layer++) {
        const float* lw1 = p[layer * 8 + 0];
        const float* lb1 = p[layer * 8 + 1];
        const float* lw2 = p[layer * 8 + 2];
        const float* lb2 = p[layer * 8 + 3];
        const float* gw1 = p[layer * 8 + 4];
        const float* gb1 = p[layer * 8 + 5];
        const float* gw2 = p[layer * 8 + 6];
        const float* gb2 = p[layer * 8 + 7];
        const float* inx = (layer == 0) ? x : H0;
        float* outp = (layer == 0) ? H0 : (float*)d_out;

        prep_all_kernel<<<640, HD>>>(lw1, lw2, gw1, gw2,
                                     WHA, WLA, W2T, WH1, WL1, WH2, WL2);

        gemm_ab_kernel<<<gemmBlocks, THREADS, AB_SMEM>>>(
            pos, inx, WHA, WLA, lb1, AH, BH);

        fill_kernel<<<fillBlocks, THREADS>>>((float4*)AGG, -FLT_MAX, NODES * HD / 4);
        edge_mma_kernel<<<GRID_EDGE, THREADS, EDGE_SMEM>>>(
            SSRC, SDST, AH, BH, W2T, lb2, AGG, total);

        gemm_gg_kernel<<<gemmBlocks, THREADS, AB_SMEM>>>(
            AGG, WH1, WL1, WH2, WL2, gb1, gb2, outp);
    }
}